// round 13
// baseline (speedup 1.0000x reference)
#include <cuda_runtime.h>
#include <math.h>
#include <stdint.h>

// Problem constants
constexpr int TT  = 2048;
constexpr int HH  = 2048;
constexpr int II  = 8192;
constexpr int EE  = 32;
constexpr int KT  = 4;
constexpr int MI  = 1408;
constexpr int CAP = 2048;

// Scratch (device globals)
__device__ float g_h1[(size_t)TT * II];
__device__ float g_act[(size_t)EE * CAP * MI];
__device__ int   g_cnt[EE];
__device__ int   g_tok[EE * CAP];
__device__ float g_wt[EE * CAP];

__device__ __forceinline__ float silu_f(float v) { return v / (1.0f + expf(-v)); }
__device__ __forceinline__ unsigned f2tf_u(float v) {
    unsigned r;
    asm("cvt.rna.tf32.f32 %0, %1;" : "=r"(r) : "f"(v));
    return r;
}
__device__ __forceinline__ uint32_t smem_u32(const void* p) {
    uint32_t a;
    asm("{ .reg .u64 t; cvta.to.shared.u64 t, %1; cvt.u32.u64 %0, t; }" : "=r"(a) : "l"(p));
    return a;
}
__device__ __forceinline__ void cpasync16(uint32_t dst, const void* src) {
    asm volatile("cp.async.cg.shared.global [%0], [%1], 16;" :: "r"(dst), "l"(src) : "memory");
}
#define CP_COMMIT() asm volatile("cp.async.commit_group;" ::: "memory")
#define CP_WAIT1()  asm volatile("cp.async.wait_group 1;" ::: "memory")
#define CP_WAIT0()  asm volatile("cp.async.wait_group 0;" ::: "memory")

__global__ void reset_kernel() {
    if (threadIdx.x < EE) g_cnt[threadIdx.x] = 0;
}

__global__ void router_kernel(const float* __restrict__ x, const float* __restrict__ gw,
                              float* __restrict__ logits) {
    int t = blockIdx.x * 8 + threadIdx.y;
    int lane = threadIdx.x;
    const float* xr = x + (size_t)t * HH;
    float acc = 0.f;
    for (int h = 0; h < HH; h += 32) {
        float xv = xr[h + lane];
        #pragma unroll
        for (int j = 0; j < 32; j++) {
            float xb = __shfl_sync(0xffffffffu, xv, j);
            acc = fmaf(xb, gw[(size_t)(h + j) * EE + lane], acc);
        }
    }
    logits[(size_t)t * EE + lane] = acc;
}

__global__ void topk_kernel(const float* __restrict__ logits) {
    int t = blockIdx.x * 8 + threadIdx.y;
    int lane = threadIdx.x;
    float cur = logits[(size_t)t * EE + lane];
    float vals[KT]; int idxs[KT];
    #pragma unroll
    for (int k = 0; k < KT; k++) {
        float bv = cur; int bi = lane;
        #pragma unroll
        for (int off = 16; off; off >>= 1) {
            float ov = __shfl_xor_sync(0xffffffffu, bv, off);
            int   oi = __shfl_xor_sync(0xffffffffu, bi, off);
            if (ov > bv || (ov == bv && oi < bi)) { bv = ov; bi = oi; }
        }
        vals[k] = bv; idxs[k] = bi;
        if (lane == bi) cur = -3.402823466e38f;
    }
    if (lane == 0) {
        float m = vals[0], s = 0.f, e[KT];
        #pragma unroll
        for (int k = 0; k < KT; k++) { e[k] = expf(vals[k] - m); s += e[k]; }
        float inv = 1.f / s;
        #pragma unroll
        for (int k = 0; k < KT; k++) {
            int ex = idxs[k];
            int slot = atomicAdd(&g_cnt[ex], 1);
            g_tok[ex * CAP + slot] = t;
            g_wt[ex * CAP + slot]  = e[k] * inv;
        }
    }
}

// ── tf32 mma.sync GEMM: CTA 128 x BNT, warp tile 64x64, THREADS = BNT (4 or 8 warps).
// cp.async 3-stage, BK=16. A smem [m][k] pitch 20; B smem [k][n] pitch BNT+8 (== 8 mod 32).
// MODE 0: g_h1 = silu(x @ ws1)   MODE 1: out = g_h1 @ ws2
// MODE 2: g_act[e] = silu(gather(x) @ w1[e])
// MODE 3: atomicAdd(out[token], w * (g_act[e] @ w2[e]))
constexpr int BM = 128, BK = 16;
constexpr int PAD_A = 20;
constexpr int A_BYTES = BM * PAD_A * 4;          // 10240
constexpr int NSTAGE = 3;

template <int MODE, int BNT>
__global__ __launch_bounds__(BNT)
void gemm_tf32(const float* __restrict__ Ain, const float* __restrict__ Bin,
               float* __restrict__ Cout, int N, int Kd) {
    constexpr int THREADS = BNT;
    constexpr int NWC     = BNT / 64;            // warps along n
    constexpr int STR_B   = BNT + 8;
    constexpr int B_BYTES = BK * STR_B * 4;
    constexpr int STAGE_BYTES = A_BYTES + B_BYTES;

    extern __shared__ char smem[];
    int e = 0, rows;
    const float* A = Ain;
    const float* B = Bin;
    const int*   tokl = nullptr;
    const float* wtl  = nullptr;
    const int row0 = blockIdx.y * BM, col0 = blockIdx.x * BNT;
    if (MODE == 2 || MODE == 3) {
        e = blockIdx.z;
        rows = g_cnt[e];
        if (row0 >= rows) return;
        tokl = g_tok + e * CAP;
        wtl  = g_wt  + e * CAP;
        if (MODE == 2) { B = Bin + (size_t)e * HH * MI; }
        else           { A = g_act + (size_t)e * CAP * MI; B = Bin + (size_t)e * MI * HH; }
    } else {
        rows = TT;
    }
    if (MODE == 1) A = g_h1;

    const uint32_t sb = smem_u32(smem);
    const int tid = threadIdx.x;
    const int lane = tid & 31, warp = tid >> 5;
    const int gid = lane >> 2, tig = lane & 3;
    const int wr = warp / NWC, wc = warp % NWC;

    // Fill mappings
    // A: 2048 elems. 128thr: row=tid, 16 floats (4 cp). 256thr: row=tid&127, 8 floats (2 cp).
    constexpr int A_CP = 2048 / THREADS / 4;     // cp.async16 per thread for A
    const int arow = tid & 127;
    const int akh  = (tid >> 7) * (A_CP * 4);    // 0 for 128thr
    const float* aRow;
    if (MODE == 2) {
        int gr = row0 + arow;
        int tok = (gr < rows) ? tokl[gr] : 0;
        aRow = A + (size_t)tok * Kd;
    } else {
        aRow = A + (size_t)(row0 + arow) * Kd;   // MODE3: memory valid up to CAP rows
    }
    // B: 16*BNT elems -> 16 floats per thread (4 cp), contiguous 64B blocks
    constexpr int BROWDIV = BNT / 16;            // threads per k-row
    const int bk = tid / BROWDIV;
    const int bn = (tid % BROWDIV) * 16;
    const float* bRow = B + (size_t)bk * N + col0 + bn;

    auto fill = [&](int st, int k0) {
        uint32_t abase = sb + st * STAGE_BYTES;
        uint32_t adst = abase + (uint32_t)(arow * PAD_A + akh) * 4;
        #pragma unroll
        for (int j = 0; j < A_CP; j++)
            cpasync16(adst + j * 16, aRow + k0 + akh + j * 4);
        uint32_t bdst = abase + A_BYTES + (uint32_t)(bk * STR_B + bn) * 4;
        const float* bsrc = bRow + (size_t)k0 * N;
        #pragma unroll
        for (int j = 0; j < 4; j++)
            cpasync16(bdst + j * 16, bsrc + j * 4);
    };

    float acc[4][8][4];
    #pragma unroll
    for (int mi = 0; mi < 4; mi++)
        #pragma unroll
        for (int ni = 0; ni < 8; ni++)
            #pragma unroll
            for (int c = 0; c < 4; c++) acc[mi][ni][c] = 0.f;

    const int nk = Kd / BK;
    fill(0, 0);  CP_COMMIT();
    fill(1, BK); CP_COMMIT();

    for (int kc = 0; kc < nk; kc++) {
        if (kc + 1 == nk) { CP_WAIT0(); } else { CP_WAIT1(); }
        __syncthreads();
        if (kc + 2 < nk) { fill((kc + 2) % NSTAGE, (kc + 2) * BK); CP_COMMIT(); }

        int st = kc % NSTAGE;
        const float* Am = (const float*)(smem + st * STAGE_BYTES);
        const float* Bk = (const float*)(smem + st * STAGE_BYTES + A_BYTES);

        #pragma unroll
        for (int ks = 0; ks < BK; ks += 8) {
            unsigned af[4][4], bf[8][2];
            #pragma unroll
            for (int mi = 0; mi < 4; mi++) {
                int r = wr * 64 + mi * 16 + gid;
                af[mi][0] = f2tf_u(Am[(r    ) * PAD_A + ks + tig    ]);
                af[mi][1] = f2tf_u(Am[(r + 8) * PAD_A + ks + tig    ]);
                af[mi][2] = f2tf_u(Am[(r    ) * PAD_A + ks + tig + 4]);
                af[mi][3] = f2tf_u(Am[(r + 8) * PAD_A + ks + tig + 4]);
            }
            #pragma unroll
            for (int ni = 0; ni < 8; ni++) {
                int c = wc * 64 + ni * 8 + gid;
                bf[ni][0] = f2tf_u(Bk[(ks + tig    ) * STR_B + c]);
                bf[ni][1] = f2tf_u(Bk[(ks + tig + 4) * STR_B + c]);
            }
            #pragma unroll
            for (int mi = 0; mi < 4; mi++)
                #pragma unroll
                for (int ni = 0; ni < 8; ni++)
                    asm volatile(
                        "mma.sync.aligned.m16n8k8.row.col.f32.tf32.tf32.f32 "
                        "{%0,%1,%2,%3}, {%4,%5,%6,%7}, {%8,%9}, {%0,%1,%2,%3};"
                        : "+f"(acc[mi][ni][0]), "+f"(acc[mi][ni][1]),
                          "+f"(acc[mi][ni][2]), "+f"(acc[mi][ni][3])
                        : "r"(af[mi][0]), "r"(af[mi][1]), "r"(af[mi][2]), "r"(af[mi][3]),
                          "r"(bf[ni][0]), "r"(bf[ni][1]));
        }
    }

    // Epilogue: direct float2 stores per fragment
    #pragma unroll
    for (int mi = 0; mi < 4; mi++) {
        #pragma unroll
        for (int half = 0; half < 2; half++) {
            int r = row0 + wr * 64 + mi * 16 + gid + half * 8;
            if ((MODE == 2 || MODE == 3) && r >= rows) continue;
            #pragma unroll
            for (int ni = 0; ni < 8; ni++) {
                int c = col0 + wc * 64 + ni * 8 + tig * 2;
                float v0 = acc[mi][ni][half * 2 + 0];
                float v1 = acc[mi][ni][half * 2 + 1];
                if (MODE == 0) {
                    float2* p = (float2*)(g_h1 + (size_t)r * II + c);
                    *p = make_float2(silu_f(v0), silu_f(v1));
                } else if (MODE == 1) {
                    float2* p = (float2*)(Cout + (size_t)r * HH + c);
                    *p = make_float2(v0, v1);
                } else if (MODE == 2) {
                    float2* p = (float2*)(g_act + ((size_t)e * CAP + r) * MI + c);
                    *p = make_float2(silu_f(v0), silu_f(v1));
                } else {
                    int tokn = tokl[r];
                    float w  = wtl[r];
                    float* p = Cout + (size_t)tokn * HH + c;
                    atomicAdd(&p[0], v0 * w);
                    atomicAdd(&p[1], v1 * w);
                }
            }
        }
    }
}

extern "C" void kernel_launch(void* const* d_in, const int* in_sizes, int n_in,
                              void* d_out, int out_size) {
    (void)in_sizes; (void)n_in; (void)out_size;
    const float* x   = (const float*)d_in[0];
    const float* gw  = (const float*)d_in[1];
    const float* w1  = (const float*)d_in[2];
    const float* w2  = (const float*)d_in[3];
    const float* ws1 = (const float*)d_in[4];
    const float* ws2 = (const float*)d_in[5];
    float* out    = (float*)d_out;
    float* logits = out + (size_t)TT * HH;

    constexpr int SM128 = NSTAGE * (A_BYTES + BK * (128 + 8) * 4);   // 56832
    constexpr int SM256 = NSTAGE * (A_BYTES + BK * (256 + 8) * 4);   // 81408
    cudaFuncSetAttribute(gemm_tf32<0, 256>, cudaFuncAttributeMaxDynamicSharedMemorySize, SM256);
    cudaFuncSetAttribute(gemm_tf32<1, 256>, cudaFuncAttributeMaxDynamicSharedMemorySize, SM256);
    cudaFuncSetAttribute(gemm_tf32<2, 128>, cudaFuncAttributeMaxDynamicSharedMemorySize, SM128);
    cudaFuncSetAttribute(gemm_tf32<3, 256>, cudaFuncAttributeMaxDynamicSharedMemorySize, SM256);

    reset_kernel<<<1, 32>>>();
    router_kernel<<<TT / 8, dim3(32, 8)>>>(x, gw, logits);
    topk_kernel<<<TT / 8, dim3(32, 8)>>>(logits);

    // expert up: N=1408 -> BN=128
    gemm_tf32<2, 128><<<dim3(MI / 128, CAP / 128, EE), 128, SM128>>>(x, w1, nullptr, MI, HH);
    // shared up: N=8192 -> BN=256
    gemm_tf32<0, 256><<<dim3(II / 256, TT / 128), 256, SM256>>>(x, ws1, nullptr, II, HH);
    // shared down: N=2048 -> BN=256
    gemm_tf32<1, 256><<<dim3(HH / 256, TT / 128), 256, SM256>>>(nullptr, ws2, out, HH, II);
    // expert down: N=2048 -> BN=256
    gemm_tf32<3, 256><<<dim3(HH / 256, CAP / 128, EE), 256, SM256>>>(nullptr, w2, out, HH, MI);
}

// round 17
// speedup vs baseline: 1.0122x; 1.0122x over previous
#include <cuda_runtime.h>
#include <math.h>
#include <stdint.h>

// Problem constants
constexpr int TT  = 2048;
constexpr int HH  = 2048;
constexpr int II  = 8192;
constexpr int EE  = 32;
constexpr int KT  = 4;
constexpr int MI  = 1408;
constexpr int CAP = 2048;

// Scratch (device globals)
__device__ float g_h1[(size_t)TT * II];
__device__ float g_act[(size_t)EE * CAP * MI];
__device__ int   g_cnt[EE];
__device__ int   g_tok[EE * CAP];
__device__ float g_wt[EE * CAP];

__device__ __forceinline__ float silu_f(float v) { return v / (1.0f + expf(-v)); }
__device__ __forceinline__ unsigned f2tf_u(float v) {
    unsigned r;
    asm("cvt.rna.tf32.f32 %0, %1;" : "=r"(r) : "f"(v));
    return r;
}
__device__ __forceinline__ uint32_t smem_u32(const void* p) {
    uint32_t a;
    asm("{ .reg .u64 t; cvta.to.shared.u64 t, %1; cvt.u32.u64 %0, t; }" : "=r"(a) : "l"(p));
    return a;
}
__device__ __forceinline__ void cpasync16(uint32_t dst, const void* src) {
    asm volatile("cp.async.cg.shared.global [%0], [%1], 16;" :: "r"(dst), "l"(src) : "memory");
}
#define CP_COMMIT() asm volatile("cp.async.commit_group;" ::: "memory")
#define CP_WAIT1()  asm volatile("cp.async.wait_group 1;" ::: "memory")
#define CP_WAIT0()  asm volatile("cp.async.wait_group 0;" ::: "memory")

__global__ void reset_kernel() {
    if (threadIdx.x < EE) g_cnt[threadIdx.x] = 0;
}

__global__ void zero_out_kernel(float* __restrict__ out) {
    size_t i = (size_t)blockIdx.x * 256 + threadIdx.x;
    out[i] = 0.f;
}

__global__ void router_kernel(const float* __restrict__ x, const float* __restrict__ gw,
                              float* __restrict__ logits) {
    int t = blockIdx.x * 8 + threadIdx.y;
    int lane = threadIdx.x;
    const float* xr = x + (size_t)t * HH;
    float acc = 0.f;
    for (int h = 0; h < HH; h += 32) {
        float xv = xr[h + lane];
        #pragma unroll
        for (int j = 0; j < 32; j++) {
            float xb = __shfl_sync(0xffffffffu, xv, j);
            acc = fmaf(xb, gw[(size_t)(h + j) * EE + lane], acc);
        }
    }
    logits[(size_t)t * EE + lane] = acc;
}

__global__ void topk_kernel(const float* __restrict__ logits) {
    int t = blockIdx.x * 8 + threadIdx.y;
    int lane = threadIdx.x;
    float cur = logits[(size_t)t * EE + lane];
    float vals[KT]; int idxs[KT];
    #pragma unroll
    for (int k = 0; k < KT; k++) {
        float bv = cur; int bi = lane;
        #pragma unroll
        for (int off = 16; off; off >>= 1) {
            float ov = __shfl_xor_sync(0xffffffffu, bv, off);
            int   oi = __shfl_xor_sync(0xffffffffu, bi, off);
            if (ov > bv || (ov == bv && oi < bi)) { bv = ov; bi = oi; }
        }
        vals[k] = bv; idxs[k] = bi;
        if (lane == bi) cur = -3.402823466e38f;
    }
    if (lane == 0) {
        float m = vals[0], s = 0.f, e[KT];
        #pragma unroll
        for (int k = 0; k < KT; k++) { e[k] = expf(vals[k] - m); s += e[k]; }
        float inv = 1.f / s;
        #pragma unroll
        for (int k = 0; k < KT; k++) {
            int ex = idxs[k];
            int slot = atomicAdd(&g_cnt[ex], 1);
            g_tok[ex * CAP + slot] = t;
            g_wt[ex * CAP + slot]  = e[k] * inv;
        }
    }
}

// ── Merged tf32 GEMMs. CTA 128x128, 128 threads (4 warps 2x2), warp tile 64x64,
// cp.async 3-stage, BK=16, A pitch 20, B pitch 136 (R9-proven config).
// PHASE 0: 1D grid 6656 = [0,5632) expert-up silu(gather(x)@w1[e])->g_act
//                       ∪ [5632,6656) shared-up silu(x@ws1)->g_h1         (K=2048 both)
// PHASE 1: 1D grid 8448 = [0,8192) expert-down atomicAdd(out, wt*(g_act@w2[e]))
//                       ∪ [8192,8448) shared-down atomicAdd(out, g_h1@ws2)
// Expert tiles come first; dead tiles exit instantly and shared tiles backfill.
constexpr int BK = 16;
constexpr int PAD_A = 20;
constexpr int A_BYTES = 128 * PAD_A * 4;         // 10240
constexpr int STR_B = 136;
constexpr int B_BYTES = BK * STR_B * 4;          // 8704
constexpr int STAGE_BYTES = A_BYTES + B_BYTES;   // 18944
constexpr int NSTAGE = 3;
constexpr int SMEM_TOTAL = NSTAGE * STAGE_BYTES; // 56832

template <int PHASE>
__global__ __launch_bounds__(128)
void gemm_merged(const float* __restrict__ x,  const float* __restrict__ w1,
                 const float* __restrict__ w2, const float* __restrict__ ws1,
                 const float* __restrict__ ws2, float* __restrict__ out) {
    extern __shared__ char smem[];
    const int idx = blockIdx.x;

    bool em;                 // expert mode?
    int e = 0, xt, yt, rows, N, Kd;
    const float* A; const float* B;
    const int* tokl = nullptr; const float* wtl = nullptr;

    if (PHASE == 0) {
        if (idx < 5632) {                        // expert up: 11 x-tiles, 16 y-tiles, 32 e
            em = true;
            e = idx / 176; int r = idx % 176; xt = r % 11; yt = r / 11;
            rows = g_cnt[e];
            if (yt * 128 >= rows) return;
            tokl = g_tok + e * CAP;
            A = x; B = w1 + (size_t)e * HH * MI; N = MI; Kd = HH;
        } else {                                 // shared up: 64 x-tiles, 16 y-tiles
            em = false;
            int j = idx - 5632; xt = j % 64; yt = j / 64;
            rows = TT; A = x; B = ws1; N = II; Kd = HH;
        }
    } else {
        if (idx < 8192) {                        // expert down: 16 x, 16 y, 32 e
            em = true;
            e = idx / 256; int r = idx % 256; xt = r % 16; yt = r / 16;
            rows = g_cnt[e];
            if (yt * 128 >= rows) return;
            tokl = g_tok + e * CAP; wtl = g_wt + e * CAP;
            A = g_act + (size_t)e * CAP * MI; B = w2 + (size_t)e * MI * HH; N = HH; Kd = MI;
        } else {                                 // shared down: 16 x, 16 y
            em = false;
            int j = idx - 8192; xt = j % 16; yt = j / 16;
            rows = TT; A = g_h1; B = ws2; N = HH; Kd = II;
        }
    }
    const int row0 = yt * 128, col0 = xt * 128;

    const uint32_t sb = smem_u32(smem);
    const int tid = threadIdx.x;
    const int lane = tid & 31, warp = tid >> 5;
    const int gid = lane >> 2, tig = lane & 3;
    const int wr = warp >> 1, wc = warp & 1;

    // Fill mappings: A row = tid (gathered for phase0 expert), 16 k-floats (4 cp.async16)
    const float* aRow;
    if (PHASE == 0 && em) {
        int gr = row0 + tid;
        int tok = (gr < rows) ? tokl[gr] : 0;
        aRow = A + (size_t)tok * Kd;
    } else {
        aRow = A + (size_t)(row0 + tid) * Kd;    // expert-down: memory valid to CAP rows
    }
    const int bk = tid >> 3, bn = (tid & 7) * 16;
    const float* bRow = B + (size_t)bk * N + col0 + bn;

    auto fill = [&](int st, int k0) {
        uint32_t abase = sb + st * STAGE_BYTES;
        uint32_t adst = abase + (uint32_t)tid * (PAD_A * 4);
        #pragma unroll
        for (int j = 0; j < 4; j++)
            cpasync16(adst + j * 16, aRow + k0 + j * 4);
        uint32_t bdst = abase + A_BYTES + (uint32_t)(bk * STR_B + bn) * 4;
        const float* bsrc = bRow + (size_t)k0 * N;
        #pragma unroll
        for (int j = 0; j < 4; j++)
            cpasync16(bdst + j * 16, bsrc + j * 4);
    };

    float acc[4][8][4];
    #pragma unroll
    for (int mi = 0; mi < 4; mi++)
        #pragma unroll
        for (int ni = 0; ni < 8; ni++)
            #pragma unroll
            for (int c = 0; c < 4; c++) acc[mi][ni][c] = 0.f;

    const int nk = Kd / BK;
    fill(0, 0);  CP_COMMIT();
    fill(1, BK); CP_COMMIT();

    for (int kc = 0; kc < nk; kc++) {
        if (kc + 1 == nk) { CP_WAIT0(); } else { CP_WAIT1(); }
        __syncthreads();
        if (kc + 2 < nk) { fill((kc + 2) % NSTAGE, (kc + 2) * BK); CP_COMMIT(); }

        int st = kc % NSTAGE;
        const float* Am = (const float*)(smem + st * STAGE_BYTES);
        const float* Bk = (const float*)(smem + st * STAGE_BYTES + A_BYTES);

        #pragma unroll
        for (int ks = 0; ks < BK; ks += 8) {
            unsigned af[4][4], bf[8][2];
            #pragma unroll
            for (int mi = 0; mi < 4; mi++) {
                int r = wr * 64 + mi * 16 + gid;
                af[mi][0] = f2tf_u(Am[(r    ) * PAD_A + ks + tig    ]);
                af[mi][1] = f2tf_u(Am[(r + 8) * PAD_A + ks + tig    ]);
                af[mi][2] = f2tf_u(Am[(r    ) * PAD_A + ks + tig + 4]);
                af[mi][3] = f2tf_u(Am[(r + 8) * PAD_A + ks + tig + 4]);
            }
            #pragma unroll
            for (int ni = 0; ni < 8; ni++) {
                int c = wc * 64 + ni * 8 + gid;
                bf[ni][0] = f2tf_u(Bk[(ks + tig    ) * STR_B + c]);
                bf[ni][1] = f2tf_u(Bk[(ks + tig + 4) * STR_B + c]);
            }
            #pragma unroll
            for (int mi = 0; mi < 4; mi++)
                #pragma unroll
                for (int ni = 0; ni < 8; ni++)
                    asm volatile(
                        "mma.sync.aligned.m16n8k8.row.col.f32.tf32.tf32.f32 "
                        "{%0,%1,%2,%3}, {%4,%5,%6,%7}, {%8,%9}, {%0,%1,%2,%3};"
                        : "+f"(acc[mi][ni][0]), "+f"(acc[mi][ni][1]),
                          "+f"(acc[mi][ni][2]), "+f"(acc[mi][ni][3])
                        : "r"(af[mi][0]), "r"(af[mi][1]), "r"(af[mi][2]), "r"(af[mi][3]),
                          "r"(bf[ni][0]), "r"(bf[ni][1]));
        }
    }

    // Epilogue
    #pragma unroll
    for (int mi = 0; mi < 4; mi++) {
        #pragma unroll
        for (int half = 0; half < 2; half++) {
            int r = row0 + wr * 64 + mi * 16 + gid + half * 8;
            if (em && r >= rows) continue;
            #pragma unroll
            for (int ni = 0; ni < 8; ni++) {
                int c = col0 + wc * 64 + ni * 8 + tig * 2;
                float v0 = acc[mi][ni][half * 2 + 0];
                float v1 = acc[mi][ni][half * 2 + 1];
                if (PHASE == 0) {
                    if (em) {
                        float2* p = (float2*)(g_act + ((size_t)e * CAP + r) * MI + c);
                        *p = make_float2(silu_f(v0), silu_f(v1));
                    } else {
                        float2* p = (float2*)(g_h1 + (size_t)r * II + c);
                        *p = make_float2(silu_f(v0), silu_f(v1));
                    }
                } else {
                    int tokn; float w;
                    if (em) { tokn = tokl[r]; w = wtl[r]; }
                    else    { tokn = r;       w = 1.f;   }
                    float* p = out + (size_t)tokn * HH + c;
                    atomicAdd(&p[0], v0 * w);
                    atomicAdd(&p[1], v1 * w);
                }
            }
        }
    }
}

extern "C" void kernel_launch(void* const* d_in, const int* in_sizes, int n_in,
                              void* d_out, int out_size) {
    (void)in_sizes; (void)n_in; (void)out_size;
    const float* x   = (const float*)d_in[0];
    const float* gw  = (const float*)d_in[1];
    const float* w1  = (const float*)d_in[2];
    const float* w2  = (const float*)d_in[3];
    const float* ws1 = (const float*)d_in[4];
    const float* ws2 = (const float*)d_in[5];
    float* out    = (float*)d_out;
    float* logits = out + (size_t)TT * HH;

    cudaFuncSetAttribute(gemm_merged<0>, cudaFuncAttributeMaxDynamicSharedMemorySize, SMEM_TOTAL);
    cudaFuncSetAttribute(gemm_merged<1>, cudaFuncAttributeMaxDynamicSharedMemorySize, SMEM_TOTAL);

    reset_kernel<<<1, 32>>>();
    zero_out_kernel<<<(TT * HH) / 256, 256>>>(out);
    router_kernel<<<TT / 8, dim3(32, 8)>>>(x, gw, logits);
    topk_kernel<<<TT / 8, dim3(32, 8)>>>(logits);

    // Phase 0: expert-up (5632 tiles) + shared-up (1024 tiles), backfilled
    gemm_merged<0><<<6656, 128, SMEM_TOTAL>>>(x, w1, w2, ws1, ws2, out);
    // Phase 1: expert-down (8192 tiles) + shared-down (256 tiles), both atomic into out
    gemm_merged<1><<<8448, 128, SMEM_TOTAL>>>(x, w1, w2, ws1, ws2, out);
}